// round 10
// baseline (speedup 1.0000x reference)
#include <cuda_runtime.h>
#include <cuda_fp16.h>
#include <math.h>

#define NN 50000
#define EE 1600000
#define DIM 128
#define HEADS 4
#define ODIM 32
#define ALPHA 0.2f
#define WPB 8
#define SCAN_B 512
#define NSCB ((NN + SCAN_B - 1) / SCAN_B)   // 98

// ---------------- device scratch ----------------
__device__ __align__(16) __half g_Hh[NN * DIM];   // fp16 features (only copy of H)
__device__ __align__(16) float  g_Hs[NN * HEADS];
__device__ __align__(16) float  g_Ht[NN * HEADS];
__device__ int g_cnt[NN];        // zero at load; re-zeroed by scan3
__device__ int g_off[NN + 1];
__device__ int g_cur[NN];
__device__ int g_csr[EE];
__device__ int g_part[NSCB];
__device__ int g_partoff[NSCB];
__device__ unsigned g_maxh[8];   // enc(max Hs_h) [0..3], enc(max Ht_h) [4..7]

__device__ __forceinline__ unsigned enc_f(float f) {
    unsigned u = __float_as_uint(f);
    return (u & 0x80000000u) ? ~u : (u | 0x80000000u);
}
__device__ __forceinline__ float dec_f(unsigned u) {
    return (u & 0x80000000u) ? __uint_as_float(u ^ 0x80000000u)
                             : __uint_as_float(~u);
}
__device__ __forceinline__ float lrelu(float x) { return x > 0.f ? x : ALPHA * x; }

// ---------------- chain A, K1: SIMT GEMM + fused scores/maxes ----------------
__global__ __launch_bounds__(256) void gemm_kernel(const float* __restrict__ X,
                                                   const float* __restrict__ W,
                                                   const float* __restrict__ Al,
                                                   const float* __restrict__ Ar) {
    if (blockIdx.x == 0 && threadIdx.x < 8) g_maxh[threadIdx.x] = 0u;
    __shared__ __align__(16) float Xs[16][132];
    __shared__ __align__(16) float Ws[16][128];
    __shared__ unsigned sm8[8];
    const int m0 = blockIdx.x * 128;
    const int tid = threadIdx.x;
    const int tx = tid & 15;
    const int ty = tid >> 4;
    if (tid < 8) sm8[tid] = 0u;

    float acc[8][8];
#pragma unroll
    for (int i = 0; i < 8; i++)
#pragma unroll
        for (int j = 0; j < 8; j++) acc[i][j] = 0.0f;

    const int head = tx >> 2;
    const int sub  = tx & 3;
    float alv[8], arv[8];
    {
        const float4* ap = (const float4*)(Al + head * ODIM + sub * 8);
        const float4* bp = (const float4*)(Ar + head * ODIM + sub * 8);
        *(float4*)(alv)     = ap[0];
        *(float4*)(alv + 4) = ap[1];
        *(float4*)(arv)     = bp[0];
        *(float4*)(arv + 4) = bp[1];
    }

    for (int k0 = 0; k0 < DIM; k0 += 16) {
#pragma unroll
        for (int j = 0; j < 2; j++) {
            int s = tid * 2 + j;
            int m = s >> 2;
            int kk4 = (s & 3) * 4;
            float4 v = make_float4(0.f, 0.f, 0.f, 0.f);
            int gm = m0 + m;
            if (gm < NN) v = *(const float4*)(X + (size_t)gm * DIM + k0 + kk4);
            Xs[kk4 + 0][m] = v.x;
            Xs[kk4 + 1][m] = v.y;
            Xs[kk4 + 2][m] = v.z;
            Xs[kk4 + 3][m] = v.w;
            int wk = s >> 5;
            int wc = (s & 31) * 4;
            *(float4*)&Ws[wk][wc] = *(const float4*)(W + (size_t)(k0 + wk) * DIM + wc);
        }
        __syncthreads();
#pragma unroll
        for (int kk = 0; kk < 16; kk++) {
            float a[8], b[8];
            *(float4*)(a)     = *(float4*)&Xs[kk][ty * 8];
            *(float4*)(a + 4) = *(float4*)&Xs[kk][ty * 8 + 4];
            *(float4*)(b)     = *(float4*)&Ws[kk][tx * 8];
            *(float4*)(b + 4) = *(float4*)&Ws[kk][tx * 8 + 4];
#pragma unroll
            for (int i = 0; i < 8; i++)
#pragma unroll
                for (int j = 0; j < 8; j++) acc[i][j] = fmaf(a[i], b[j], acc[i][j]);
        }
        __syncthreads();
    }

    float mymax_s = -1e30f, mymax_t = -1e30f;
#pragma unroll
    for (int i = 0; i < 8; i++) {
        int gm = m0 + ty * 8 + i;
        if (gm < NN) {
            __half2 h0 = __float22half2_rn(make_float2(acc[i][0], acc[i][1]));
            __half2 h1 = __float22half2_rn(make_float2(acc[i][2], acc[i][3]));
            __half2 h2 = __float22half2_rn(make_float2(acc[i][4], acc[i][5]));
            __half2 h3 = __float22half2_rn(make_float2(acc[i][6], acc[i][7]));
            __half2* hp = (__half2*)(g_Hh + (size_t)gm * DIM + tx * 8);
            hp[0] = h0; hp[1] = h1; hp[2] = h2; hp[3] = h3;
            float s = 0.f, t = 0.f;
#pragma unroll
            for (int c = 0; c < 8; c++) {
                s = fmaf(acc[i][c], alv[c], s);
                t = fmaf(acc[i][c], arv[c], t);
            }
            s += __shfl_xor_sync(0xffffffffu, s, 1);
            t += __shfl_xor_sync(0xffffffffu, t, 1);
            s += __shfl_xor_sync(0xffffffffu, s, 2);
            t += __shfl_xor_sync(0xffffffffu, t, 2);
            if (sub == 0) {
                g_Hs[(size_t)gm * 4 + head] = s;
                g_Ht[(size_t)gm * 4 + head] = t;
                mymax_s = fmaxf(mymax_s, s);
                mymax_t = fmaxf(mymax_t, t);
            }
        }
    }
    if (sub == 0) {
        atomicMax(&sm8[head],     enc_f(mymax_s));
        atomicMax(&sm8[4 + head], enc_f(mymax_t));
    }
    __syncthreads();
    if (tid < 8) atomicMax(&g_maxh[tid], sm8[tid]);
}

// ---------------- chain B, K3: histogram ----------------
__global__ void hist_kernel(const int* __restrict__ ei) {
    int e = blockIdx.x * blockDim.x + threadIdx.x;
    if (e < EE) atomicAdd(&g_cnt[ei[e]], 1);
}

// ---------------- chain B, K4a: block partial sums ----------------
__global__ __launch_bounds__(SCAN_B) void scan1_kernel() {
    __shared__ int sw[SCAN_B / 32];
    int i = blockIdx.x * SCAN_B + threadIdx.x;
    int v = (i < NN) ? g_cnt[i] : 0;
#pragma unroll
    for (int o = 16; o > 0; o >>= 1) v += __shfl_xor_sync(0xffffffffu, v, o);
    int lane = threadIdx.x & 31, wid = threadIdx.x >> 5;
    if (lane == 0) sw[wid] = v;
    __syncthreads();
    if (wid == 0) {
        v = (lane < SCAN_B / 32) ? sw[lane] : 0;
#pragma unroll
        for (int o = 8; o > 0; o >>= 1) v += __shfl_xor_sync(0xffffffffu, v, o);
        if (lane == 0) g_part[blockIdx.x] = v;
    }
}

// ---------------- chain B, K4b: scan the 98 partials ----------------
__global__ __launch_bounds__(128) void scan2_kernel() {
    __shared__ int s[128];
    int t = threadIdx.x;
    s[t] = (t < NSCB) ? g_part[t] : 0;
    __syncthreads();
#pragma unroll
    for (int off = 1; off < 128; off <<= 1) {
        int v = (t >= off) ? s[t - off] : 0;
        __syncthreads();
        s[t] += v;
        __syncthreads();
    }
    if (t < NSCB) g_partoff[t] = (t == 0) ? 0 : s[t - 1];
}

// ---------------- chain B, K4c: in-block exclusive scan + write offsets ----------------
__global__ __launch_bounds__(SCAN_B) void scan3_kernel() {
    __shared__ int s[SCAN_B];
    int t = threadIdx.x;
    int i = blockIdx.x * SCAN_B + t;
    int v = (i < NN) ? g_cnt[i] : 0;
    s[t] = v;
    __syncthreads();
#pragma unroll
    for (int off = 1; off < SCAN_B; off <<= 1) {
        int u = (t >= off) ? s[t - off] : 0;
        __syncthreads();
        s[t] += u;
        __syncthreads();
    }
    if (i < NN) {
        int prefix = g_partoff[blockIdx.x] + s[t] - v;
        g_off[i] = prefix;
        g_cur[i] = prefix;
        g_cnt[i] = 0;
        if (i == NN - 1) g_off[NN] = EE;
    }
}

// ---------------- chain B, K5: scatter edges into CSR ----------------
__global__ void scatter_kernel(const int* __restrict__ ei) {
    int e = blockIdx.x * blockDim.x + threadIdx.x;
    if (e < EE) {
        int src = ei[e];
        int tgt = ei[EE + e];
        int p = atomicAdd(&g_cur[src], 1);
        g_csr[p] = tgt;
    }
}

// ---------------- join, K6: fused softmax + aggregation + ELU ----------------
// 16 lanes per row (LDG.128 each), 2 rows per warp-step.
__device__ __forceinline__ void agg_row(int r, int cg, int hh,
                                        const int* s_tgt, const float* s_e,
                                        float* acc) {
    int t = s_tgt[r];
    float ej = s_e[r * 4 + hh];
    float4 raw = *(const float4*)(g_Hh + (size_t)t * DIM + cg * 8);  // 8 halves
    const __half2* h2 = (const __half2*)&raw;
    float2 f0 = __half22float2(h2[0]);
    float2 f1 = __half22float2(h2[1]);
    float2 f2 = __half22float2(h2[2]);
    float2 f3 = __half22float2(h2[3]);
    acc[0] = fmaf(ej, f0.x, acc[0]);
    acc[1] = fmaf(ej, f0.y, acc[1]);
    acc[2] = fmaf(ej, f1.x, acc[2]);
    acc[3] = fmaf(ej, f1.y, acc[3]);
    acc[4] = fmaf(ej, f2.x, acc[4]);
    acc[5] = fmaf(ej, f2.y, acc[5]);
    acc[6] = fmaf(ej, f3.x, acc[6]);
    acc[7] = fmaf(ej, f3.y, acc[7]);
}

__global__ __launch_bounds__(WPB * 32) void agg_kernel(float* __restrict__ out) {
    __shared__ int   s_tgt[WPB][32];
    __shared__ float s_e[WPB][32 * 4];
    int wid  = threadIdx.x >> 5;
    int lane = threadIdx.x & 31;
    int node = blockIdx.x * WPB + wid;
    if (node >= NN) return;
    int half = lane >> 4;        // which row of the pair
    int cg   = lane & 15;        // col group: cols cg*8 .. cg*8+7
    int hh   = cg >> 2;          // head of those cols
    int he   = lane >> 3;        // head index for edge-score lanes (e4 path)
    int start = g_off[node];
    int end   = g_off[node + 1];
    float4 M4;
    M4.x = lrelu(dec_f(g_maxh[0]) + dec_f(g_maxh[4]));
    M4.y = lrelu(dec_f(g_maxh[1]) + dec_f(g_maxh[5]));
    M4.z = lrelu(dec_f(g_maxh[2]) + dec_f(g_maxh[6]));
    M4.w = lrelu(dec_f(g_maxh[3]) + dec_f(g_maxh[7]));
    float4 hs = *(const float4*)(g_Hs + (size_t)node * 4);

    float acc[8];
#pragma unroll
    for (int c = 0; c < 8; c++) acc[c] = 0.f;
    float4 dsum = make_float4(0.f, 0.f, 0.f, 0.f);

    for (int base = start; base < end; base += 32) {
        int cnt = min(32, end - base);
        int tgt = 0;
        float4 e4 = make_float4(0.f, 0.f, 0.f, 0.f);
        if (lane < cnt) {
            tgt = g_csr[base + lane];
            float4 ht = *(const float4*)(g_Ht + (size_t)tgt * 4);
            e4.x = __expf(lrelu(hs.x + ht.x) - M4.x);
            e4.y = __expf(lrelu(hs.y + ht.y) - M4.y);
            e4.z = __expf(lrelu(hs.z + ht.z) - M4.z);
            e4.w = __expf(lrelu(hs.w + ht.w) - M4.w);
            dsum.x += e4.x; dsum.y += e4.y; dsum.z += e4.z; dsum.w += e4.w;
        }
        s_tgt[wid][lane] = tgt;
        *(float4*)&s_e[wid][lane * 4] = e4;
        __syncwarp();
        if (cnt == 32) {
#pragma unroll
            for (int j = 0; j < 32; j += 2)
                agg_row(j + half, cg, hh, s_tgt[wid], s_e[wid], acc);
        } else {
            for (int j = 0; j < cnt; j += 2) {
                int r = j + half;
                if (r < cnt) agg_row(r, cg, hh, s_tgt[wid], s_e[wid], acc);
            }
        }
        __syncwarp();
    }

    // combine even/odd row halves (lane <-> lane^16)
#pragma unroll
    for (int c = 0; c < 8; c++)
        acc[c] += __shfl_xor_sync(0xffffffffu, acc[c], 16);

    // full-warp reduce of dsum (every lane ends with totals)
#pragma unroll
    for (int o = 16; o > 0; o >>= 1) {
        dsum.x += __shfl_xor_sync(0xffffffffu, dsum.x, o);
        dsum.y += __shfl_xor_sync(0xffffffffu, dsum.y, o);
        dsum.z += __shfl_xor_sync(0xffffffffu, dsum.z, o);
        dsum.w += __shfl_xor_sync(0xffffffffu, dsum.w, o);
    }

    if (half == 0) {
        float dh = (hh == 0) ? dsum.x : (hh == 1) ? dsum.y : (hh == 2) ? dsum.z : dsum.w;
        float sc = 1.0f / (dh + 1e-8f);
        float4 o0, o1;
        o0.x = acc[0] * sc; o0.y = acc[1] * sc; o0.z = acc[2] * sc; o0.w = acc[3] * sc;
        o1.x = acc[4] * sc; o1.y = acc[5] * sc; o1.z = acc[6] * sc; o1.w = acc[7] * sc;
        o0.x = o0.x > 0.f ? o0.x : expm1f(o0.x);
        o0.y = o0.y > 0.f ? o0.y : expm1f(o0.y);
        o0.z = o0.z > 0.f ? o0.z : expm1f(o0.z);
        o0.w = o0.w > 0.f ? o0.w : expm1f(o0.w);
        o1.x = o1.x > 0.f ? o1.x : expm1f(o1.x);
        o1.y = o1.y > 0.f ? o1.y : expm1f(o1.y);
        o1.z = o1.z > 0.f ? o1.z : expm1f(o1.z);
        o1.w = o1.w > 0.f ? o1.w : expm1f(o1.w);
        float* op = out + (size_t)node * DIM + cg * 8;
        *(float4*)(op)     = o0;
        *(float4*)(op + 4) = o1;
    }
}

extern "C" void kernel_launch(void* const* d_in, const int* in_sizes, int n_in,
                              void* d_out, int out_size) {
    const float* X  = (const float*)d_in[0];
    const int* EI   = (const int*)d_in[1];
    const float* W  = (const float*)d_in[2];
    const float* Al = (const float*)d_in[3];
    const float* Ar = (const float*)d_in[4];
    float* out = (float*)d_out;

    static cudaStream_t sA = nullptr, sB = nullptr;
    static cudaEvent_t evFork = nullptr, evA = nullptr, evB = nullptr;
    if (sA == nullptr) {
        cudaStreamCreateWithFlags(&sA, cudaStreamNonBlocking);
        cudaStreamCreateWithFlags(&sB, cudaStreamNonBlocking);
        cudaEventCreateWithFlags(&evFork, cudaEventDisableTiming);
        cudaEventCreateWithFlags(&evA, cudaEventDisableTiming);
        cudaEventCreateWithFlags(&evB, cudaEventDisableTiming);
    }

    cudaEventRecord(evFork, 0);
    cudaStreamWaitEvent(sA, evFork, 0);
    cudaStreamWaitEvent(sB, evFork, 0);

    // chain A: features + fused scores
    gemm_kernel<<<(NN + 127) / 128, 256, 0, sA>>>(X, W, Al, Ar);
    cudaEventRecord(evA, sA);

    // chain B: CSR build
    hist_kernel<<<(EE + 255) / 256, 256, 0, sB>>>(EI);
    scan1_kernel<<<NSCB, SCAN_B, 0, sB>>>();
    scan2_kernel<<<1, 128, 0, sB>>>();
    scan3_kernel<<<NSCB, SCAN_B, 0, sB>>>();
    scatter_kernel<<<(EE + 255) / 256, 256, 0, sB>>>(EI);
    cudaEventRecord(evB, sB);

    cudaStreamWaitEvent(0, evA, 0);
    cudaStreamWaitEvent(0, evB, 0);
    agg_kernel<<<(NN + WPB - 1) / WPB, WPB * 32>>>(out);
}

// round 11
// speedup vs baseline: 1.0659x; 1.0659x over previous
#include <cuda_runtime.h>
#include <cuda_fp16.h>
#include <math.h>

#define NN 50000
#define EE 1600000
#define DIM 128
#define HEADS 4
#define ODIM 32
#define ALPHA 0.2f
#define WPB 8
#define SCAN_B 512
#define NSCB ((NN + SCAN_B - 1) / SCAN_B)   // 98

// ---------------- device scratch ----------------
__device__ __align__(16) __half g_Hh[NN * DIM];   // fp16 features (only copy of H)
__device__ __align__(16) float  g_Hs[NN * HEADS];
__device__ __align__(16) float  g_Ht[NN * HEADS];
__device__ int g_cnt[NN];        // zero at load; re-zeroed by scan3
__device__ int g_off[NN + 1];
__device__ int g_cur[NN];
__device__ int g_csr[EE];
__device__ int g_part[NSCB];
__device__ int g_partoff[NSCB];
__device__ unsigned g_maxh[8];   // enc(max Hs_h) [0..3], enc(max Ht_h) [4..7]

__device__ __forceinline__ unsigned enc_f(float f) {
    unsigned u = __float_as_uint(f);
    return (u & 0x80000000u) ? ~u : (u | 0x80000000u);
}
__device__ __forceinline__ float dec_f(unsigned u) {
    return (u & 0x80000000u) ? __uint_as_float(u ^ 0x80000000u)
                             : __uint_as_float(~u);
}
__device__ __forceinline__ float lrelu(float x) { return x > 0.f ? x : ALPHA * x; }

__device__ __forceinline__ unsigned to_tf32(float x) {
    unsigned u;
    asm("cvt.rna.tf32.f32 %0, %1;" : "=r"(u) : "f"(x));
    return u;
}
__device__ __forceinline__ void mma_tf32(float* c, const unsigned* a,
                                         unsigned b0, unsigned b1) {
    asm volatile(
        "mma.sync.aligned.m16n8k8.row.col.f32.tf32.tf32.f32 "
        "{%0,%1,%2,%3}, {%4,%5,%6,%7}, {%8,%9}, {%0,%1,%2,%3};\n"
        : "+f"(c[0]), "+f"(c[1]), "+f"(c[2]), "+f"(c[3])
        : "r"(a[0]), "r"(a[1]), "r"(a[2]), "r"(a[3]), "r"(b0), "r"(b1));
}

// ---------------- chain A, K1: tf32 tensor GEMM + fused scores/maxes ----------------
// Block tile 128x128, 8 warps (wr 0-3, wc 0-1), warp tile 32x64.
__global__ __launch_bounds__(256) void gemm_tc(const float* __restrict__ X,
                                               const float* __restrict__ W,
                                               const float* __restrict__ Al,
                                               const float* __restrict__ Ar) {
    if (blockIdx.x == 0 && threadIdx.x < 8) g_maxh[threadIdx.x] = 0u;
    __shared__ float Xs[128][36];   // bank(g,tig)=4g+tig distinct
    __shared__ float Ws[32][136];   // bank(tig,g)=8tig+g distinct; rows 16B aligned
    __shared__ unsigned sm8[8];
    const int tid  = threadIdx.x;
    const int lane = tid & 31;
    const int warp = tid >> 5;
    const int wr = warp >> 1;
    const int wc = warp & 1;
    const int g   = lane >> 2;
    const int tig = lane & 3;
    const int m0 = blockIdx.x * 128;
    if (tid < 8) sm8[tid] = 0u;

    float c[2][8][4];
#pragma unroll
    for (int mi = 0; mi < 2; mi++)
#pragma unroll
        for (int ni = 0; ni < 8; ni++)
#pragma unroll
            for (int j = 0; j < 4; j++) c[mi][ni][j] = 0.f;

    for (int kc = 0; kc < DIM; kc += 32) {
        __syncthreads();
        // stage X tile [128 x 32]
        for (int idx = tid; idx < 128 * 8; idx += 256) {
            int row = idx >> 3;
            int c4  = (idx & 7) * 4;
            int gm = m0 + row;
            float4 v = make_float4(0.f, 0.f, 0.f, 0.f);
            if (gm < NN) v = *(const float4*)(X + (size_t)gm * DIM + kc + c4);
            Xs[row][c4 + 0] = v.x;
            Xs[row][c4 + 1] = v.y;
            Xs[row][c4 + 2] = v.z;
            Xs[row][c4 + 3] = v.w;
        }
        // stage W tile [32 x 128]
        for (int idx = tid; idx < 32 * 32; idx += 256) {
            int row = idx >> 5;
            int c4  = (idx & 31) * 4;
            *(float4*)&Ws[row][c4] = *(const float4*)(W + (size_t)(kc + row) * DIM + c4);
        }
        __syncthreads();

#pragma unroll
        for (int k8 = 0; k8 < 32; k8 += 8) {
            unsigned ah[2][4], al[2][4];
#pragma unroll
            for (int mi = 0; mi < 2; mi++) {
                int r = wr * 32 + mi * 16;
                float x0 = Xs[r + g][k8 + tig];
                float x1 = Xs[r + g + 8][k8 + tig];
                float x2 = Xs[r + g][k8 + tig + 4];
                float x3 = Xs[r + g + 8][k8 + tig + 4];
                ah[mi][0] = to_tf32(x0);
                ah[mi][1] = to_tf32(x1);
                ah[mi][2] = to_tf32(x2);
                ah[mi][3] = to_tf32(x3);
                al[mi][0] = to_tf32(x0 - __uint_as_float(ah[mi][0]));
                al[mi][1] = to_tf32(x1 - __uint_as_float(ah[mi][1]));
                al[mi][2] = to_tf32(x2 - __uint_as_float(ah[mi][2]));
                al[mi][3] = to_tf32(x3 - __uint_as_float(ah[mi][3]));
            }
            unsigned bh[8][2], bl[8][2];
#pragma unroll
            for (int ni = 0; ni < 8; ni++) {
                int n = wc * 64 + ni * 8 + g;
                float w0 = Ws[k8 + tig][n];
                float w1 = Ws[k8 + tig + 4][n];
                bh[ni][0] = to_tf32(w0);
                bh[ni][1] = to_tf32(w1);
                bl[ni][0] = to_tf32(w0 - __uint_as_float(bh[ni][0]));
                bl[ni][1] = to_tf32(w1 - __uint_as_float(bh[ni][1]));
            }
#pragma unroll
            for (int mi = 0; mi < 2; mi++)
#pragma unroll
                for (int ni = 0; ni < 8; ni++) {
                    mma_tf32(c[mi][ni], ah[mi], bh[ni][0], bh[ni][1]);
                    mma_tf32(c[mi][ni], ah[mi], bl[ni][0], bl[ni][1]);
                    mma_tf32(c[mi][ni], al[mi], bh[ni][0], bh[ni][1]);
                }
        }
    }

    // ---- epilogue: fp16 store + fused scores ----
    const int head0 = wc * 2, head1 = wc * 2 + 1;
    float alv0[8], arv0[8], alv1[8], arv1[8];
#pragma unroll
    for (int ni = 0; ni < 4; ni++)
#pragma unroll
        for (int j = 0; j < 2; j++) {
            int o = ni * 8 + tig * 2 + j;
            alv0[ni * 2 + j] = Al[head0 * ODIM + o];
            arv0[ni * 2 + j] = Ar[head0 * ODIM + o];
            alv1[ni * 2 + j] = Al[head1 * ODIM + o];
            arv1[ni * 2 + j] = Ar[head1 * ODIM + o];
        }
    float mx_s0 = -1e30f, mx_t0 = -1e30f, mx_s1 = -1e30f, mx_t1 = -1e30f;
#pragma unroll
    for (int mi = 0; mi < 2; mi++)
#pragma unroll
        for (int half = 0; half < 2; half++) {
            int row = m0 + wr * 32 + mi * 16 + g + 8 * half;
            float s0 = 0.f, t0 = 0.f, s1 = 0.f, t1 = 0.f;
            if (row < NN) {
#pragma unroll
                for (int ni = 0; ni < 8; ni++) {
                    float v0 = c[mi][ni][half * 2];
                    float v1 = c[mi][ni][half * 2 + 1];
                    *(__half2*)(g_Hh + (size_t)row * DIM + wc * 64 + ni * 8 + tig * 2) =
                        __floats2half2_rn(v0, v1);
                    if (ni < 4) {
                        s0 = fmaf(v0, alv0[ni * 2], s0);
                        s0 = fmaf(v1, alv0[ni * 2 + 1], s0);
                        t0 = fmaf(v0, arv0[ni * 2], t0);
                        t0 = fmaf(v1, arv0[ni * 2 + 1], t0);
                    } else {
                        s1 = fmaf(v0, alv1[(ni - 4) * 2], s1);
                        s1 = fmaf(v1, alv1[(ni - 4) * 2 + 1], s1);
                        t1 = fmaf(v0, arv1[(ni - 4) * 2], t1);
                        t1 = fmaf(v1, arv1[(ni - 4) * 2 + 1], t1);
                    }
                }
            }
            s0 += __shfl_xor_sync(0xffffffffu, s0, 1);
            t0 += __shfl_xor_sync(0xffffffffu, t0, 1);
            s1 += __shfl_xor_sync(0xffffffffu, s1, 1);
            t1 += __shfl_xor_sync(0xffffffffu, t1, 1);
            s0 += __shfl_xor_sync(0xffffffffu, s0, 2);
            t0 += __shfl_xor_sync(0xffffffffu, t0, 2);
            s1 += __shfl_xor_sync(0xffffffffu, s1, 2);
            t1 += __shfl_xor_sync(0xffffffffu, t1, 2);
            if (tig == 0 && row < NN) {
                g_Hs[(size_t)row * 4 + head0] = s0;
                g_Ht[(size_t)row * 4 + head0] = t0;
                g_Hs[(size_t)row * 4 + head1] = s1;
                g_Ht[(size_t)row * 4 + head1] = t1;
                mx_s0 = fmaxf(mx_s0, s0);
                mx_t0 = fmaxf(mx_t0, t0);
                mx_s1 = fmaxf(mx_s1, s1);
                mx_t1 = fmaxf(mx_t1, t1);
            }
        }
    if (tig == 0) {
        atomicMax(&sm8[head0],     enc_f(mx_s0));
        atomicMax(&sm8[4 + head0], enc_f(mx_t0));
        atomicMax(&sm8[head1],     enc_f(mx_s1));
        atomicMax(&sm8[4 + head1], enc_f(mx_t1));
    }
    __syncthreads();
    if (tid < 8) atomicMax(&g_maxh[tid], sm8[tid]);
}

// ---------------- chain B, K3: histogram (4 edges/thread) ----------------
__global__ void hist_kernel(const int* __restrict__ ei) {
    int e4 = (blockIdx.x * blockDim.x + threadIdx.x) * 4;
    if (e4 + 3 < EE) {
        int4 s = *(const int4*)(ei + e4);
        atomicAdd(&g_cnt[s.x], 1);
        atomicAdd(&g_cnt[s.y], 1);
        atomicAdd(&g_cnt[s.z], 1);
        atomicAdd(&g_cnt[s.w], 1);
    } else {
        for (int e = e4; e < EE; e++) atomicAdd(&g_cnt[ei[e]], 1);
    }
}

// ---------------- chain B, K4a: block partial sums ----------------
__global__ __launch_bounds__(SCAN_B) void scan1_kernel() {
    __shared__ int sw[SCAN_B / 32];
    int i = blockIdx.x * SCAN_B + threadIdx.x;
    int v = (i < NN) ? g_cnt[i] : 0;
#pragma unroll
    for (int o = 16; o > 0; o >>= 1) v += __shfl_xor_sync(0xffffffffu, v, o);
    int lane = threadIdx.x & 31, wid = threadIdx.x >> 5;
    if (lane == 0) sw[wid] = v;
    __syncthreads();
    if (wid == 0) {
        v = (lane < SCAN_B / 32) ? sw[lane] : 0;
#pragma unroll
        for (int o = 8; o > 0; o >>= 1) v += __shfl_xor_sync(0xffffffffu, v, o);
        if (lane == 0) g_part[blockIdx.x] = v;
    }
}

// ---------------- chain B, K4b: scan the 98 partials ----------------
__global__ __launch_bounds__(128) void scan2_kernel() {
    __shared__ int s[128];
    int t = threadIdx.x;
    s[t] = (t < NSCB) ? g_part[t] : 0;
    __syncthreads();
#pragma unroll
    for (int off = 1; off < 128; off <<= 1) {
        int v = (t >= off) ? s[t - off] : 0;
        __syncthreads();
        s[t] += v;
        __syncthreads();
    }
    if (t < NSCB) g_partoff[t] = (t == 0) ? 0 : s[t - 1];
}

// ---------------- chain B, K4c: in-block exclusive scan + write offsets ----------------
__global__ __launch_bounds__(SCAN_B) void scan3_kernel() {
    __shared__ int s[SCAN_B];
    int t = threadIdx.x;
    int i = blockIdx.x * SCAN_B + t;
    int v = (i < NN) ? g_cnt[i] : 0;
    s[t] = v;
    __syncthreads();
#pragma unroll
    for (int off = 1; off < SCAN_B; off <<= 1) {
        int u = (t >= off) ? s[t - off] : 0;
        __syncthreads();
        s[t] += u;
        __syncthreads();
    }
    if (i < NN) {
        int prefix = g_partoff[blockIdx.x] + s[t] - v;
        g_off[i] = prefix;
        g_cur[i] = prefix;
        g_cnt[i] = 0;
        if (i == NN - 1) g_off[NN] = EE;
    }
}

// ---------------- chain B, K5: scatter (4 edges/thread) ----------------
__global__ void scatter_kernel(const int* __restrict__ ei) {
    int e4 = (blockIdx.x * blockDim.x + threadIdx.x) * 4;
    if (e4 + 3 < EE) {
        int4 s = *(const int4*)(ei + e4);
        int4 t = *(const int4*)(ei + EE + e4);
        int p0 = atomicAdd(&g_cur[s.x], 1);
        int p1 = atomicAdd(&g_cur[s.y], 1);
        int p2 = atomicAdd(&g_cur[s.z], 1);
        int p3 = atomicAdd(&g_cur[s.w], 1);
        g_csr[p0] = t.x;
        g_csr[p1] = t.y;
        g_csr[p2] = t.z;
        g_csr[p3] = t.w;
    } else {
        for (int e = e4; e < EE; e++) {
            int p = atomicAdd(&g_cur[ei[e]], 1);
            g_csr[p] = ei[EE + e];
        }
    }
}

// ---------------- join, K6: fused softmax + aggregation + ELU (R9 layout) ----------------
__device__ __forceinline__ void agg_step(int j, int lane, int h,
                                         const int* s_tgt, const float* s_e,
                                         float4& acc) {
    int t = s_tgt[j];
    float ej = s_e[j * 4 + h];
    const __half2* hp = (const __half2*)(g_Hh + (size_t)t * DIM + lane * 4);
    __half2 a = hp[0], b = hp[1];
    float2 fa = __half22float2(a);
    float2 fb = __half22float2(b);
    acc.x = fmaf(ej, fa.x, acc.x);
    acc.y = fmaf(ej, fa.y, acc.y);
    acc.z = fmaf(ej, fb.x, acc.z);
    acc.w = fmaf(ej, fb.y, acc.w);
}

__global__ __launch_bounds__(WPB * 32) void agg_kernel(float* __restrict__ out) {
    __shared__ int   s_tgt[WPB][32];
    __shared__ float s_e[WPB][32 * 4];
    int wid  = threadIdx.x >> 5;
    int lane = threadIdx.x & 31;
    int node = blockIdx.x * WPB + wid;
    if (node >= NN) return;
    int h = lane >> 3;
    int start = g_off[node];
    int end   = g_off[node + 1];
    float4 M4;
    M4.x = lrelu(dec_f(g_maxh[0]) + dec_f(g_maxh[4]));
    M4.y = lrelu(dec_f(g_maxh[1]) + dec_f(g_maxh[5]));
    M4.z = lrelu(dec_f(g_maxh[2]) + dec_f(g_maxh[6]));
    M4.w = lrelu(dec_f(g_maxh[3]) + dec_f(g_maxh[7]));
    float4 hs = *(const float4*)(g_Hs + (size_t)node * 4);

    float4 acc0 = make_float4(0.f, 0.f, 0.f, 0.f);
    float4 acc1 = make_float4(0.f, 0.f, 0.f, 0.f);
    float4 acc2 = make_float4(0.f, 0.f, 0.f, 0.f);
    float4 acc3 = make_float4(0.f, 0.f, 0.f, 0.f);
    float4 dsum = make_float4(0.f, 0.f, 0.f, 0.f);

    for (int base = start; base < end; base += 32) {
        int cnt = min(32, end - base);
        int tgt = 0;
        float4 e4 = make_float4(0.f, 0.f, 0.f, 0.f);
        if (lane < cnt) {
            tgt = g_csr[base + lane];
            float4 ht = *(const float4*)(g_Ht + (size_t)tgt * 4);
            e4.x = __expf(lrelu(hs.x + ht.x) - M4.x);
            e4.y = __expf(lrelu(hs.y + ht.y) - M4.y);
            e4.z = __expf(lrelu(hs.z + ht.z) - M4.z);
            e4.w = __expf(lrelu(hs.w + ht.w) - M4.w);
            dsum.x += e4.x; dsum.y += e4.y; dsum.z += e4.z; dsum.w += e4.w;
        }
        s_tgt[wid][lane] = tgt;
        *(float4*)&s_e[wid][lane * 4] = e4;
        __syncwarp();
        if (cnt == 32) {
#pragma unroll
            for (int j = 0; j < 32; j += 4) {
                agg_step(j,     lane, h, s_tgt[wid], s_e[wid], acc0);
                agg_step(j + 1, lane, h, s_tgt[wid], s_e[wid], acc1);
                agg_step(j + 2, lane, h, s_tgt[wid], s_e[wid], acc2);
                agg_step(j + 3, lane, h, s_tgt[wid], s_e[wid], acc3);
            }
        } else {
#pragma unroll 4
            for (int j = 0; j < cnt; j++)
                agg_step(j, lane, h, s_tgt[wid], s_e[wid], acc0);
        }
        __syncwarp();
    }

    float4 acc = make_float4(acc0.x + acc1.x + acc2.x + acc3.x,
                             acc0.y + acc1.y + acc2.y + acc3.y,
                             acc0.z + acc1.z + acc2.z + acc3.z,
                             acc0.w + acc1.w + acc2.w + acc3.w);
#pragma unroll
    for (int o = 16; o > 0; o >>= 1) {
        dsum.x += __shfl_xor_sync(0xffffffffu, dsum.x, o);
        dsum.y += __shfl_xor_sync(0xffffffffu, dsum.y, o);
        dsum.z += __shfl_xor_sync(0xffffffffu, dsum.z, o);
        dsum.w += __shfl_xor_sync(0xffffffffu, dsum.w, o);
    }
    float dh = (h == 0) ? dsum.x : (h == 1) ? dsum.y : (h == 2) ? dsum.z : dsum.w;
    float sc = 1.0f / (dh + 1e-8f);
    acc.x *= sc; acc.y *= sc; acc.z *= sc; acc.w *= sc;
    acc.x = acc.x > 0.f ? acc.x : expm1f(acc.x);
    acc.y = acc.y > 0.f ? acc.y : expm1f(acc.y);
    acc.z = acc.z > 0.f ? acc.z : expm1f(acc.z);
    acc.w = acc.w > 0.f ? acc.w : expm1f(acc.w);
    *(float4*)(out + (size_t)node * DIM + lane * 4) = acc;
}

extern "C" void kernel_launch(void* const* d_in, const int* in_sizes, int n_in,
                              void* d_out, int out_size) {
    const float* X  = (const float*)d_in[0];
    const int* EI   = (const int*)d_in[1];
    const float* W  = (const float*)d_in[2];
    const float* Al = (const float*)d_in[3];
    const float* Ar = (const float*)d_in[4];
    float* out = (float*)d_out;

    static cudaStream_t sA = nullptr, sB = nullptr;
    static cudaEvent_t evFork = nullptr, evA = nullptr, evB = nullptr;
    if (sA == nullptr) {
        cudaStreamCreateWithFlags(&sA, cudaStreamNonBlocking);
        cudaStreamCreateWithFlags(&sB, cudaStreamNonBlocking);
        cudaEventCreateWithFlags(&evFork, cudaEventDisableTiming);
        cudaEventCreateWithFlags(&evA, cudaEventDisableTiming);
        cudaEventCreateWithFlags(&evB, cudaEventDisableTiming);
    }

    cudaEventRecord(evFork, 0);
    cudaStreamWaitEvent(sA, evFork, 0);
    cudaStreamWaitEvent(sB, evFork, 0);

    // chain A: features + fused scores (tf32 tensor cores)
    gemm_tc<<<(NN + 127) / 128, 256, 0, sA>>>(X, W, Al, Ar);
    cudaEventRecord(evA, sA);

    // chain B: CSR build
    hist_kernel<<<(EE / 4 + 255) / 256, 256, 0, sB>>>(EI);
    scan1_kernel<<<NSCB, SCAN_B, 0, sB>>>();
    scan2_kernel<<<1, 128, 0, sB>>>();
    scan3_kernel<<<NSCB, SCAN_B, 0, sB>>>();
    scatter_kernel<<<(EE / 4 + 255) / 256, 256, 0, sB>>>(EI);
    cudaEventRecord(evB, sB);

    cudaStreamWaitEvent(0, evA, 0);
    cudaStreamWaitEvent(0, evB, 0);
    agg_kernel<<<(NN + WPB - 1) / WPB, WPB * 32>>>(out);
}

// round 12
// speedup vs baseline: 1.5653x; 1.4685x over previous
#include <cuda_runtime.h>
#include <cuda_fp16.h>
#include <math.h>

#define NN 50000
#define EE 1600000
#define DIM 128
#define HEADS 4
#define ODIM 32
#define ALPHA 0.2f
#define WPB 8
#define SCAN_B 512
#define NSCB ((NN + SCAN_B - 1) / SCAN_B)   // 98

// ---------------- device scratch ----------------
__device__ __align__(16) __half g_Xh[NN * DIM];   // fp16 copy of X
__device__ __align__(16) __half g_Hh[NN * DIM];   // fp16 features
__device__ __align__(16) float  g_Hs[NN * HEADS];
__device__ __align__(16) float  g_Ht[NN * HEADS];
__device__ int g_cnt[NN];        // zero at load; re-zeroed by scan3
__device__ int g_off[NN + 1];
__device__ int g_cur[NN];
__device__ int g_csr[EE];
__device__ int g_part[NSCB];
__device__ int g_partoff[NSCB];
__device__ unsigned g_maxh[8];

__device__ __forceinline__ unsigned enc_f(float f) {
    unsigned u = __float_as_uint(f);
    return (u & 0x80000000u) ? ~u : (u | 0x80000000u);
}
__device__ __forceinline__ float dec_f(unsigned u) {
    return (u & 0x80000000u) ? __uint_as_float(u ^ 0x80000000u)
                             : __uint_as_float(~u);
}
__device__ __forceinline__ float lrelu(float x) { return x > 0.f ? x : ALPHA * x; }

__device__ __forceinline__ void mma_f16(float* c, const unsigned* a,
                                        unsigned b0, unsigned b1) {
    asm volatile(
        "mma.sync.aligned.m16n8k16.row.col.f32.f16.f16.f32 "
        "{%0,%1,%2,%3}, {%4,%5,%6,%7}, {%8,%9}, {%0,%1,%2,%3};\n"
        : "+f"(c[0]), "+f"(c[1]), "+f"(c[2]), "+f"(c[3])
        : "r"(a[0]), "r"(a[1]), "r"(a[2]), "r"(a[3]), "r"(b0), "r"(b1));
}

// ---------------- chain A, K0: X -> fp16 ----------------
__global__ void xcvt_kernel(const float* __restrict__ X) {
    int i = blockIdx.x * blockDim.x + threadIdx.x;   // one per 8 elems
    if (i < NN * DIM / 8) {
        const float4* p = (const float4*)X + (size_t)i * 2;
        float4 v0 = p[0], v1 = p[1];
        __half2 h[4];
        h[0] = __floats2half2_rn(v0.x, v0.y);
        h[1] = __floats2half2_rn(v0.z, v0.w);
        h[2] = __floats2half2_rn(v1.x, v1.y);
        h[3] = __floats2half2_rn(v1.z, v1.w);
        *(uint4*)(g_Xh + (size_t)i * 8) = *(uint4*)h;
    }
}

// ---------------- chain A, K1: fp16 HMMA GEMM + fused scores/maxes ----------------
// Block tile 128x128, 8 warps (wr 0-3 rows of 32, wc 0-1 cols of 64).
__global__ __launch_bounds__(256) void gemm_f16(const float* __restrict__ W,
                                                const float* __restrict__ Al,
                                                const float* __restrict__ Ar) {
    if (blockIdx.x == 0 && threadIdx.x < 8) g_maxh[threadIdx.x] = 0u;
    __shared__ __align__(16) __half Xs[128][72];   // pad 8 halves
    __shared__ __align__(16) __half Wt[128][72];   // W transposed: [n][k]
    __shared__ unsigned sm8[8];
    const int tid  = threadIdx.x;
    const int lane = tid & 31;
    const int warp = tid >> 5;
    const int wr = warp >> 1;
    const int wc = warp & 1;
    const int g   = lane >> 2;
    const int tig = lane & 3;
    const int m0 = blockIdx.x * 128;
    if (tid < 8) sm8[tid] = 0u;

    float c[2][8][4];
#pragma unroll
    for (int mi = 0; mi < 2; mi++)
#pragma unroll
        for (int ni = 0; ni < 8; ni++)
#pragma unroll
            for (int j = 0; j < 4; j++) c[mi][ni][j] = 0.f;

    for (int kc = 0; kc < DIM; kc += 64) {
        __syncthreads();
        // stage Xh tile [128 rows x 64 k] (16B vector copies)
        for (int idx = tid; idx < 128 * 8; idx += 256) {
            int row = idx >> 3;
            int c8  = (idx & 7) * 8;
            int gm = m0 + row;
            uint4 v = make_uint4(0u, 0u, 0u, 0u);
            if (gm < NN) v = *(const uint4*)(g_Xh + (size_t)gm * DIM + kc + c8);
            *(uint4*)&Xs[row][c8] = v;
        }
        // stage W tile transposed: Wt[n][k], fp32->fp16 on the fly
        for (int idx = tid; idx < 64 * 32; idx += 256) {
            int k  = idx >> 5;
            int n4 = (idx & 31) * 4;
            float4 w = *(const float4*)(W + (size_t)(kc + k) * DIM + n4);
            Wt[n4 + 0][k] = __float2half(w.x);
            Wt[n4 + 1][k] = __float2half(w.y);
            Wt[n4 + 2][k] = __float2half(w.z);
            Wt[n4 + 3][k] = __float2half(w.w);
        }
        __syncthreads();

#pragma unroll
        for (int ks = 0; ks < 4; ks++) {
            const int k0 = ks * 16;
            unsigned a[2][4];
#pragma unroll
            for (int mi = 0; mi < 2; mi++) {
                int r = wr * 32 + mi * 16;
                a[mi][0] = *(const unsigned*)&Xs[r + g][k0 + tig * 2];
                a[mi][1] = *(const unsigned*)&Xs[r + g + 8][k0 + tig * 2];
                a[mi][2] = *(const unsigned*)&Xs[r + g][k0 + tig * 2 + 8];
                a[mi][3] = *(const unsigned*)&Xs[r + g + 8][k0 + tig * 2 + 8];
            }
#pragma unroll
            for (int ni = 0; ni < 8; ni++) {
                int n = wc * 64 + ni * 8 + g;
                unsigned b0 = *(const unsigned*)&Wt[n][k0 + tig * 2];
                unsigned b1 = *(const unsigned*)&Wt[n][k0 + tig * 2 + 8];
                mma_f16(c[0][ni], a[0], b0, b1);
                mma_f16(c[1][ni], a[1], b0, b1);
            }
        }
    }

    // ---- epilogue: fp16 store + fused scores (validated in R11) ----
    const int head0 = wc * 2, head1 = wc * 2 + 1;
    float alv0[8], arv0[8], alv1[8], arv1[8];
#pragma unroll
    for (int ni = 0; ni < 4; ni++)
#pragma unroll
        for (int j = 0; j < 2; j++) {
            int o = ni * 8 + tig * 2 + j;
            alv0[ni * 2 + j] = Al[head0 * ODIM + o];
            arv0[ni * 2 + j] = Ar[head0 * ODIM + o];
            alv1[ni * 2 + j] = Al[head1 * ODIM + o];
            arv1[ni * 2 + j] = Ar[head1 * ODIM + o];
        }
    float mx_s0 = -1e30f, mx_t0 = -1e30f, mx_s1 = -1e30f, mx_t1 = -1e30f;
#pragma unroll
    for (int mi = 0; mi < 2; mi++)
#pragma unroll
        for (int half = 0; half < 2; half++) {
            int row = m0 + wr * 32 + mi * 16 + g + 8 * half;
            float s0 = 0.f, t0 = 0.f, s1 = 0.f, t1 = 0.f;
            if (row < NN) {
#pragma unroll
                for (int ni = 0; ni < 8; ni++) {
                    float v0 = c[mi][ni][half * 2];
                    float v1 = c[mi][ni][half * 2 + 1];
                    *(__half2*)(g_Hh + (size_t)row * DIM + wc * 64 + ni * 8 + tig * 2) =
                        __floats2half2_rn(v0, v1);
                    if (ni < 4) {
                        s0 = fmaf(v0, alv0[ni * 2], s0);
                        s0 = fmaf(v1, alv0[ni * 2 + 1], s0);
                        t0 = fmaf(v0, arv0[ni * 2], t0);
                        t0 = fmaf(v1, arv0[ni * 2 + 1], t0);
                    } else {
                        s1 = fmaf(v0, alv1[(ni - 4) * 2], s1);
                        s1 = fmaf(v1, alv1[(ni - 4) * 2 + 1], s1);
                        t1 = fmaf(v0, arv1[(ni - 4) * 2], t1);
                        t1 = fmaf(v1, arv1[(ni - 4) * 2 + 1], t1);
                    }
                }
            }
            s0 += __shfl_xor_sync(0xffffffffu, s0, 1);
            t0 += __shfl_xor_sync(0xffffffffu, t0, 1);
            s1 += __shfl_xor_sync(0xffffffffu, s1, 1);
            t1 += __shfl_xor_sync(0xffffffffu, t1, 1);
            s0 += __shfl_xor_sync(0xffffffffu, s0, 2);
            t0 += __shfl_xor_sync(0xffffffffu, t0, 2);
            s1 += __shfl_xor_sync(0xffffffffu, s1, 2);
            t1 += __shfl_xor_sync(0xffffffffu, t1, 2);
            if (tig == 0 && row < NN) {
                g_Hs[(size_t)row * 4 + head0] = s0;
                g_Ht[(size_t)row * 4 + head0] = t0;
                g_Hs[(size_t)row * 4 + head1] = s1;
                g_Ht[(size_t)row * 4 + head1] = t1;
                mx_s0 = fmaxf(mx_s0, s0);
                mx_t0 = fmaxf(mx_t0, t0);
                mx_s1 = fmaxf(mx_s1, s1);
                mx_t1 = fmaxf(mx_t1, t1);
            }
        }
    if (tig == 0) {
        atomicMax(&sm8[head0],     enc_f(mx_s0));
        atomicMax(&sm8[4 + head0], enc_f(mx_t0));
        atomicMax(&sm8[head1],     enc_f(mx_s1));
        atomicMax(&sm8[4 + head1], enc_f(mx_t1));
    }
    __syncthreads();
    if (tid < 8) atomicMax(&g_maxh[tid], sm8[tid]);
}

// ---------------- chain B, K3: histogram ----------------
__global__ void hist_kernel(const int* __restrict__ ei) {
    int e = blockIdx.x * blockDim.x + threadIdx.x;
    if (e < EE) atomicAdd(&g_cnt[ei[e]], 1);
}

// ---------------- chain B, K4a: block partial sums ----------------
__global__ __launch_bounds__(SCAN_B) void scan1_kernel() {
    __shared__ int sw[SCAN_B / 32];
    int i = blockIdx.x * SCAN_B + threadIdx.x;
    int v = (i < NN) ? g_cnt[i] : 0;
#pragma unroll
    for (int o = 16; o > 0; o >>= 1) v += __shfl_xor_sync(0xffffffffu, v, o);
    int lane = threadIdx.x & 31, wid = threadIdx.x >> 5;
    if (lane == 0) sw[wid] = v;
    __syncthreads();
    if (wid == 0) {
        v = (lane < SCAN_B / 32) ? sw[lane] : 0;
#pragma unroll
        for (int o = 8; o > 0; o >>= 1) v += __shfl_xor_sync(0xffffffffu, v, o);
        if (lane == 0) g_part[blockIdx.x] = v;
    }
}

// ---------------- chain B, K4b: scan the 98 partials ----------------
__global__ __launch_bounds__(128) void scan2_kernel() {
    __shared__ int s[128];
    int t = threadIdx.x;
    s[t] = (t < NSCB) ? g_part[t] : 0;
    __syncthreads();
#pragma unroll
    for (int off = 1; off < 128; off <<= 1) {
        int v = (t >= off) ? s[t - off] : 0;
        __syncthreads();
        s[t] += v;
        __syncthreads();
    }
    if (t < NSCB) g_partoff[t] = (t == 0) ? 0 : s[t - 1];
}

// ---------------- chain B, K4c: in-block exclusive scan + write offsets ----------------
__global__ __launch_bounds__(SCAN_B) void scan3_kernel() {
    __shared__ int s[SCAN_B];
    int t = threadIdx.x;
    int i = blockIdx.x * SCAN_B + t;
    int v = (i < NN) ? g_cnt[i] : 0;
    s[t] = v;
    __syncthreads();
#pragma unroll
    for (int off = 1; off < SCAN_B; off <<= 1) {
        int u = (t >= off) ? s[t - off] : 0;
        __syncthreads();
        s[t] += u;
        __syncthreads();
    }
    if (i < NN) {
        int prefix = g_partoff[blockIdx.x] + s[t] - v;
        g_off[i] = prefix;
        g_cur[i] = prefix;
        g_cnt[i] = 0;
        if (i == NN - 1) g_off[NN] = EE;
    }
}

// ---------------- chain B, K5: scatter edges into CSR ----------------
__global__ void scatter_kernel(const int* __restrict__ ei) {
    int e = blockIdx.x * blockDim.x + threadIdx.x;
    if (e < EE) {
        int src = ei[e];
        int tgt = ei[EE + e];
        int p = atomicAdd(&g_cur[src], 1);
        g_csr[p] = tgt;
    }
}

// ---------------- join, K6: fused softmax + aggregation + ELU (R9 layout) ----------------
__device__ __forceinline__ void agg_step(int j, int lane, int h,
                                         const int* s_tgt, const float* s_e,
                                         float4& acc) {
    int t = s_tgt[j];
    float ej = s_e[j * 4 + h];
    const __half2* hp = (const __half2*)(g_Hh + (size_t)t * DIM + lane * 4);
    __half2 a = hp[0], b = hp[1];
    float2 fa = __half22float2(a);
    float2 fb = __half22float2(b);
    acc.x = fmaf(ej, fa.x, acc.x);
    acc.y = fmaf(ej, fa.y, acc.y);
    acc.z = fmaf(ej, fb.x, acc.z);
    acc.w = fmaf(ej, fb.y, acc.w);
}

__global__ __launch_bounds__(WPB * 32) void agg_kernel(float* __restrict__ out) {
    __shared__ int   s_tgt[WPB][32];
    __shared__ float s_e[WPB][32 * 4];
    int wid  = threadIdx.x >> 5;
    int lane = threadIdx.x & 31;
    int node = blockIdx.x * WPB + wid;
    if (node >= NN) return;
    int h = lane >> 3;
    int start = g_off[node];
    int end   = g_off[node + 1];
    float4 M4;
    M4.x = lrelu(dec_f(g_maxh[0]) + dec_f(g_maxh[4]));
    M4.y = lrelu(dec_f(g_maxh[1]) + dec_f(g_maxh[5]));
    M4.z = lrelu(dec_f(g_maxh[2]) + dec_f(g_maxh[6]));
    M4.w = lrelu(dec_f(g_maxh[3]) + dec_f(g_maxh[7]));
    float4 hs = *(const float4*)(g_Hs + (size_t)node * 4);

    float4 acc0 = make_float4(0.f, 0.f, 0.f, 0.f);
    float4 acc1 = make_float4(0.f, 0.f, 0.f, 0.f);
    float4 acc2 = make_float4(0.f, 0.f, 0.f, 0.f);
    float4 acc3 = make_float4(0.f, 0.f, 0.f, 0.f);
    float4 dsum = make_float4(0.f, 0.f, 0.f, 0.f);

    for (int base = start; base < end; base += 32) {
        int cnt = min(32, end - base);
        int tgt = 0;
        float4 e4 = make_float4(0.f, 0.f, 0.f, 0.f);
        if (lane < cnt) {
            tgt = g_csr[base + lane];
            float4 ht = *(const float4*)(g_Ht + (size_t)tgt * 4);
            e4.x = __expf(lrelu(hs.x + ht.x) - M4.x);
            e4.y = __expf(lrelu(hs.y + ht.y) - M4.y);
            e4.z = __expf(lrelu(hs.z + ht.z) - M4.z);
            e4.w = __expf(lrelu(hs.w + ht.w) - M4.w);
            dsum.x += e4.x; dsum.y += e4.y; dsum.z += e4.z; dsum.w += e4.w;
        }
        s_tgt[wid][lane] = tgt;
        *(float4*)&s_e[wid][lane * 4] = e4;
        __syncwarp();
        if (cnt == 32) {
#pragma unroll
            for (int j = 0; j < 32; j += 4) {
                agg_step(j,     lane, h, s_tgt[wid], s_e[wid], acc0);
                agg_step(j + 1, lane, h, s_tgt[wid], s_e[wid], acc1);
                agg_step(j + 2, lane, h, s_tgt[wid], s_e[wid], acc2);
                agg_step(j + 3, lane, h, s_tgt[wid], s_e[wid], acc3);
            }
        } else {
#pragma unroll 4
            for (int j = 0; j < cnt; j++)
                agg_step(j, lane, h, s_tgt[wid], s_e[wid], acc0);
        }
        __syncwarp();
    }

    float4 acc = make_float4(acc0.x + acc1.x + acc2.x + acc3.x,
                             acc0.y + acc1.y + acc2.y + acc3.y,
                             acc0.z + acc1.z + acc2.z + acc3.z,
                             acc0.w + acc1.w + acc2.w + acc3.w);
#pragma unroll
    for (int o = 16; o > 0; o >>= 1) {
        dsum.x += __shfl_xor_sync(0xffffffffu, dsum.x, o);
        dsum.y += __shfl_xor_sync(0xffffffffu, dsum.y, o);
        dsum.z += __shfl_xor_sync(0xffffffffu, dsum.z, o);
        dsum.w += __shfl_xor_sync(0xffffffffu, dsum.w, o);
    }
    float dh = (h == 0) ? dsum.x : (h == 1) ? dsum.y : (h == 2) ? dsum.z : dsum.w;
    float sc = 1.0f / (dh + 1e-8f);
    acc.x *= sc; acc.y *= sc; acc.z *= sc; acc.w *= sc;
    acc.x = acc.x > 0.f ? acc.x : expm1f(acc.x);
    acc.y = acc.y > 0.f ? acc.y : expm1f(acc.y);
    acc.z = acc.z > 0.f ? acc.z : expm1f(acc.z);
    acc.w = acc.w > 0.f ? acc.w : expm1f(acc.w);
    *(float4*)(out + (size_t)node * DIM + lane * 4) = acc;
}

extern "C" void kernel_launch(void* const* d_in, const int* in_sizes, int n_in,
                              void* d_out, int out_size) {
    const float* X  = (const float*)d_in[0];
    const int* EI   = (const int*)d_in[1];
    const float* W  = (const float*)d_in[2];
    const float* Al = (const float*)d_in[3];
    const float* Ar = (const float*)d_in[4];
    float* out = (float*)d_out;

    static cudaStream_t sA = nullptr, sB = nullptr;
    static cudaEvent_t evFork = nullptr, evA = nullptr, evB = nullptr;
    if (sA == nullptr) {
        cudaStreamCreateWithFlags(&sA, cudaStreamNonBlocking);
        cudaStreamCreateWithFlags(&sB, cudaStreamNonBlocking);
        cudaEventCreateWithFlags(&evFork, cudaEventDisableTiming);
        cudaEventCreateWithFlags(&evA, cudaEventDisableTiming);
        cudaEventCreateWithFlags(&evB, cudaEventDisableTiming);
    }

    cudaEventRecord(evFork, 0);
    cudaStreamWaitEvent(sA, evFork, 0);
    cudaStreamWaitEvent(sB, evFork, 0);

    // chain A: X->fp16, then fp16 HMMA GEMM + fused scores
    xcvt_kernel<<<(NN * DIM / 8 + 255) / 256, 256, 0, sA>>>(X);
    gemm_f16<<<(NN + 127) / 128, 256, 0, sA>>>(W, Al, Ar);
    cudaEventRecord(evA, sA);

    // chain B: CSR build
    hist_kernel<<<(EE + 255) / 256, 256, 0, sB>>>(EI);
    scan1_kernel<<<NSCB, SCAN_B, 0, sB>>>();
    scan2_kernel<<<1, 128, 0, sB>>>();
    scan3_kernel<<<NSCB, SCAN_B, 0, sB>>>();
    scatter_kernel<<<(EE + 255) / 256, 256, 0, sB>>>(EI);
    cudaEventRecord(evB, sB);

    cudaStreamWaitEvent(0, evA, 0);
    cudaStreamWaitEvent(0, evB, 0);
    agg_kernel<<<(NN + WPB - 1) / WPB, WPB * 32>>>(out);
}